// round 15
// baseline (speedup 1.0000x reference)
#include <cuda_runtime.h>
#include <cuda_bf16.h>
#include <cuda_fp16.h>
#include <math.h>
#include <stdint.h>

#define NN 50000
#define EE 100000
#define MPAD 100096   // EE padded to multiple of 128
// H = 32, ED = 1024, K_RWSE = 16

typedef __nv_bfloat16 bf16;

#define BSCALE 16.0f            // pre-scale for edge_proj_w before e4m3 quantization
#define BSCALE_INV (1.0f / 16.0f)

// ---------------- scratch (device globals; no allocations allowed) ----------------
__device__ uint8_t  g_W8[(size_t)EE * 1024];    // edge-conditioned weights, e4m3 (~102MB)
__device__ uint8_t  g_A8[(size_t)MPAD * 1024];  // e_feat in e4m3, padded rows zero (~102MB)
__device__ uint8_t  g_Bt8[1024 * 1024];         // edge_proj_w^T * 16 in e4m3 (1MB)
__device__ float g_gate[EE];
__device__ float g_deg[NN];
__device__ float g_degc[NN];
__device__ float g_rwse[NN * 16];
__device__ float g_nf[NN * 32];
__device__ float g_outA[NN * 32];
__device__ float g_outB[NN * 32];
__device__ float g_neigh[NN * 32];

// ---------------- helpers ----------------
__device__ __forceinline__ uint32_t s2u(const void* p) {
    return (uint32_t)__cvta_generic_to_shared(p);
}

// pack 2 floats -> 2 e4m3 bytes (byte order a,b)
__device__ __forceinline__ uint16_t f2_to_e4m3(float a, float b) {
    uint16_t r;
    asm("cvt.rn.satfinite.e4m3x2.f32 %0, %1, %2;" : "=h"(r) : "f"(b), "f"(a));
    return r;
}

// pack 4 floats -> 4 e4m3 bytes, byte order a,b,c,d
__device__ __forceinline__ uint32_t f4_to_e4m3(float a, float b, float c, float d) {
    uint16_t lo = f2_to_e4m3(a, b);
    uint16_t hi = f2_to_e4m3(c, d);
    return (uint32_t)lo | ((uint32_t)hi << 16);
}

// unpack 2 e4m3 bytes -> float2
__device__ __forceinline__ float2 e4m3x2_to_f2(uint16_t v) {
    uint32_t h2;
    asm("cvt.rn.f16x2.e4m3x2 %0, %1;" : "=r"(h2) : "h"(v));
    __half2 hh = *reinterpret_cast<__half2*>(&h2);
    return __half22float2(hh);
}

__device__ __forceinline__ void mma_fp8(float* c, const uint32_t* a, const uint32_t* b) {
    asm volatile(
        "mma.sync.aligned.m16n8k32.row.col.f32.e4m3.e4m3.f32 "
        "{%0,%1,%2,%3}, {%4,%5,%6,%7}, {%8,%9}, {%0,%1,%2,%3};"
        : "+f"(c[0]), "+f"(c[1]), "+f"(c[2]), "+f"(c[3])
        : "r"(a[0]), "r"(a[1]), "r"(a[2]), "r"(a[3]), "r"(b[0]), "r"(b[1]));
}

__device__ __forceinline__ void mbar_init(uint32_t mbar, uint32_t cnt) {
    asm volatile("mbarrier.init.shared.b64 [%0], %1;" :: "r"(mbar), "r"(cnt) : "memory");
}
__device__ __forceinline__ void mbar_expect_tx(uint32_t mbar, uint32_t bytes) {
    asm volatile("mbarrier.arrive.expect_tx.shared.b64 _, [%0], %1;"
                 :: "r"(mbar), "r"(bytes) : "memory");
}
__device__ __forceinline__ void mbar_wait(uint32_t mbar, uint32_t ph) {
    asm volatile(
        "{\n\t.reg .pred P;\n\t"
        "W%=:\n\t"
        "mbarrier.try_wait.parity.shared.b64 P, [%0], %1;\n\t"
        "@!P bra W%=;\n\t}"
        :: "r"(mbar), "r"(ph) : "memory");
}
__device__ __forceinline__ void bulk_ld(uint32_t dst, const void* src, uint32_t bytes,
                                        uint32_t mbar) {
    asm volatile(
        "cp.async.bulk.shared::cta.global.mbarrier::complete_tx::bytes [%0], [%1], %2, [%3];"
        :: "r"(dst), "l"(src), "r"(bytes), "r"(mbar) : "memory");
}

// ---------------- small utility kernels ----------------
__global__ void k_zero(float* p, int n) {
    int i = blockIdx.x * blockDim.x + threadIdx.x;
    if (i < n) p[i] = 0.f;
}

__global__ void k_deg(const int* __restrict__ dst) {
    int e = blockIdx.x * blockDim.x + threadIdx.x;
    if (e < EE) atomicAdd(&g_deg[dst[e]], 1.0f);
}

__global__ void k_degc() {
    int i = blockIdx.x * blockDim.x + threadIdx.x;
    if (i < NN) {
        float d = g_deg[i];
        float dc = (d == 0.f) ? 1.f : d;
        g_degc[i] = dc;
        g_rwse[i * 16] = dc;   // col 0 of RWSE = degc
    }
}

// fused scatter: applies normalization of previous column on read
__global__ void k_rwse_scatter(const int* __restrict__ src, const int* __restrict__ dst, int k) {
    int e = blockIdx.x * blockDim.x + threadIdx.x;
    if (e >= EE) return;
    int s = src[e];
    float v = g_rwse[s * 16 + (k - 1)];
    if (k > 1) v /= g_degc[s];
    atomicAdd(&g_rwse[dst[e] * 16 + k], v);
}

// ---------------- convert e_feat -> e4m3 (padded rows zeroed) ----------------
__global__ void k_convA8(const float* __restrict__ A) {
    int i = blockIdx.x * blockDim.x + threadIdx.x;     // one 16B output per thread
    if (i >= MPAD * 64) return;
    int r = i >> 6;
    int c16 = (i & 63) << 4;
    uint32_t o[4];
    if (r < EE) {
        const float* p = A + (size_t)r * 1024 + c16;
#pragma unroll
        for (int j = 0; j < 4; j++) {
            float4 v = *(const float4*)(p + 4 * j);
            o[j] = f4_to_e4m3(v.x, v.y, v.z, v.w);
        }
    } else {
        o[0] = o[1] = o[2] = o[3] = 0u;
    }
    *(uint4*)(g_A8 + (size_t)r * 1024 + c16) = *(uint4*)o;
}

// ---------------- transpose + scale + convert edge_proj_w -> g_Bt8 [N][K] e4m3 ----------------
__global__ void k_transB8(const float* __restrict__ B) {
    __shared__ float t[32][33];
    int x0 = blockIdx.x * 32, y0 = blockIdx.y * 32;
    int tx = threadIdx.x, ty = threadIdx.y;  // 32 x 8
#pragma unroll
    for (int i = 0; i < 32; i += 8)
        t[ty + i][tx] = B[(size_t)(y0 + ty + i) * 1024 + x0 + tx];
    __syncthreads();
#pragma unroll
    for (int i = 0; i < 32; i += 8) {
        float v = t[tx][ty + i] * BSCALE;
        uint16_t pk = f2_to_e4m3(v, 0.f);
        g_Bt8[(size_t)(x0 + ty + i) * 1024 + y0 + tx] = (uint8_t)(pk & 0xFF);
    }
}

// ---------------- gate: sigmoid(A8 @ gate_w + gate_b), one warp per edge ----------------
__global__ void k_gate8(const float* __restrict__ gw, const float* __restrict__ gb) {
    int t = blockIdx.x * blockDim.x + threadIdx.x;
    int e = t >> 5;
    int lane = t & 31;
    if (e >= EE) return;
    const uint8_t* row = g_A8 + (size_t)e * 1024;
    float s = 0.f;
#pragma unroll
    for (int j = 0; j < 16; j++) {
        uint16_t pk = *(const uint16_t*)(row + j * 64 + 2 * lane);
        float2 v = e4m3x2_to_f2(pk);
        float2 g = *(const float2*)(gw + j * 64 + 2 * lane);
        s += v.x * g.x + v.y * g.y;
    }
#pragma unroll
    for (int off = 16; off > 0; off >>= 1)
        s += __shfl_down_sync(0xffffffffu, s, off);
    if (lane == 0) {
        float x = s + gb[0];
        g_gate[e] = 1.f / (1.f + expf(-x));
    }
}

// ---------------- fp8 tensor-core GEMM: cp.async.bulk row loads (8x fewer load instrs) ----------------
// C(MPAD,1024) = g_A8 @ g_Bt8^T * (1/16) ; epilogue e4m3 -> g_W8
// Block tile 128x256, K-chunk 128B. 8 warps, warp tile 64x64, 2-stage mbarrier pipeline.
// Smem rows: 128B data + 16B pad = 144B = 36 words; frag LDS conflict-free (4g+t4 pattern).
#define BM 128
#define BN 256
#define BKB 128                           // K per chunk, bytes (= elements)
#define SROWB 144                         // smem row stride, bytes
#define STAGE_BYTES ((BM + BN) * SROWB)   // 55296 B
#define STAGE_TX ((BM + BN) * 128)        // 49152 B actually transferred per chunk
#define SMEM_DYN (16 + 2 * STAGE_BYTES)   // 110608 B (16B for 2 mbarriers)

__global__ void __launch_bounds__(256, 1) k_gemm_fp8(const float* __restrict__ bias) {
    extern __shared__ uint8_t smem[];
    const uint32_t mbar_base = s2u(smem);          // mbar0 @ +0, mbar1 @ +8
    uint8_t* tiles = smem + 16;
    const int t = threadIdx.x;
    const int l = t & 31, w = t >> 5;
    const int wm = w & 1, wn = w >> 1;     // 2 warps M x 4 warps N
    const int g = l >> 2, t4 = l & 3;
    const int row0 = blockIdx.y * BM;
    const int col0 = blockIdx.x * BN;

    if (t == 0) {
        mbar_init(mbar_base, 1);
        mbar_init(mbar_base + 8, 1);
    }
    __syncthreads();

    float acc[4][8][4];
#pragma unroll
    for (int mt = 0; mt < 4; mt++)
#pragma unroll
        for (int nt = 0; nt < 8; nt++)
#pragma unroll
            for (int r = 0; r < 4; r++) acc[mt][nt][r] = 0.f;

    // cooperative bulk-row issue: 384 rows (128 A + 256 B), 128B each
    auto issue_chunk = [&](int kb, int buf) {
        uint32_t mbar = mbar_base + 8 * buf;
        if (t == 0) mbar_expect_tx(mbar, STAGE_TX);
        uint32_t dst_base = s2u(tiles) + buf * STAGE_BYTES;
#pragma unroll
        for (int o = 0; o < 2; o++) {
            int r = t + o * 256;
            if (r < BM + BN) {
                uint32_t dst = dst_base + (uint32_t)r * SROWB;
                const uint8_t* src = (r < BM)
                    ? g_A8 + (size_t)(row0 + r) * 1024 + kb
                    : g_Bt8 + (size_t)(col0 + (r - BM)) * 1024 + kb;
                bulk_ld(dst, src, 128, mbar);
            }
        }
    };

    issue_chunk(0, 0);
    issue_chunk(BKB, 1);

    const int NCH = 1024 / BKB;  // 8
    for (int c = 0; c < NCH; c++) {
        int buf = c & 1;
        mbar_wait(mbar_base + 8 * buf, (c >> 1) & 1);

        const uint32_t* As32 = (const uint32_t*)(tiles + buf * STAGE_BYTES);
        const uint32_t* Bs32 = As32 + BM * (SROWB / 4);
#pragma unroll
        for (int ks = 0; ks < 4; ks++) {           // k32 per mma, 128B chunk -> 4 iters
            const int kw = ks * 8 + t4;            // word index in 32-word row
            uint32_t a[4][4];
#pragma unroll
            for (int mt = 0; mt < 4; mt++) {
                int rw = wm * 64 + mt * 16 + g;
                a[mt][0] = As32[rw * 36 + kw];
                a[mt][1] = As32[(rw + 8) * 36 + kw];
                a[mt][2] = As32[rw * 36 + kw + 4];
                a[mt][3] = As32[(rw + 8) * 36 + kw + 4];
            }
            uint32_t b[8][2];
#pragma unroll
            for (int nt = 0; nt < 8; nt++) {
                int nr = wn * 64 + nt * 8 + g;
                b[nt][0] = Bs32[nr * 36 + kw];
                b[nt][1] = Bs32[nr * 36 + kw + 4];
            }
#pragma unroll
            for (int mt = 0; mt < 4; mt++)
#pragma unroll
                for (int nt = 0; nt < 8; nt++)
                    mma_fp8(acc[mt][nt], a[mt], b[nt]);
        }
        __syncthreads();                           // all warps done with buf -> safe to refill
        if (c + 2 < NCH)
            issue_chunk((c + 2) * BKB, buf);
    }

    // epilogue: e4m3(relu(acc/16 + bias) * gate) -> g_W8
#pragma unroll
    for (int mt = 0; mt < 4; mt++) {
        int r0 = row0 + wm * 64 + mt * 16 + g;
        int r1 = r0 + 8;
        float ga0 = (r0 < EE) ? g_gate[r0] : 0.f;
        float ga1 = (r1 < EE) ? g_gate[r1] : 0.f;
#pragma unroll
        for (int nt = 0; nt < 8; nt++) {
            int cc = col0 + wn * 64 + nt * 8 + 2 * t4;
            float2 bb = *(const float2*)&bias[cc];
            if (r0 < EE) {
                float x0 = fmaxf(acc[mt][nt][0] * BSCALE_INV + bb.x, 0.f) * ga0;
                float x1 = fmaxf(acc[mt][nt][1] * BSCALE_INV + bb.y, 0.f) * ga0;
                *(uint16_t*)(g_W8 + (size_t)r0 * 1024 + cc) = f2_to_e4m3(x0, x1);
            }
            if (r1 < EE) {
                float x0 = fmaxf(acc[mt][nt][2] * BSCALE_INV + bb.x, 0.f) * ga1;
                float x1 = fmaxf(acc[mt][nt][3] * BSCALE_INV + bb.y, 0.f) * ga1;
                *(uint16_t*)(g_W8 + (size_t)r1 * 1024 + cc) = f2_to_e4m3(x0, x1);
            }
        }
    }
}

// ---------------- lin0 (applies RWSE normalization on read) ----------------
__global__ void k_lin0(const float* __restrict__ n_feat, const float* __restrict__ lw,
                       const float* __restrict__ lb) {
    __shared__ float s_w[1024];
    __shared__ float s_b[32];
    for (int i = threadIdx.x; i < 1024; i += blockDim.x) s_w[i] = lw[i];
    if (threadIdx.x < 32) s_b[threadIdx.x] = lb[threadIdx.x];
    __syncthreads();
    int i = blockIdx.x * blockDim.x + threadIdx.x;
    if (i >= NN) return;
    float dc = g_degc[i];
    float nf[32];
#pragma unroll
    for (int h = 0; h < 16; h++) nf[h] = n_feat[i * 16 + h];
    nf[16] = g_rwse[i * 16];
#pragma unroll
    for (int h = 1; h < 16; h++) nf[16 + h] = g_rwse[i * 16 + h] / dc;
#pragma unroll
    for (int h = 0; h < 32; h++) g_nf[i * 32 + h] = nf[h];
#pragma unroll
    for (int j = 0; j < 32; j++) {
        float a = s_b[j];
#pragma unroll
        for (int h = 0; h < 32; h++) a += nf[h] * s_w[h * 32 + j];
        g_outA[i * 32 + j] = fmaxf(a, 0.f);
    }
}

// ---------------- msg: warp per edge, W in e4m3 ----------------
__global__ void k_msg(const int* __restrict__ src, const int* __restrict__ dst,
                      const float* __restrict__ cur) {
    int t = blockIdx.x * blockDim.x + threadIdx.x;
    int e = t >> 5;
    int lane = t & 31;
    if (e >= EE) return;
    int s = src[e];
    float v = cur[s * 32 + lane];
    const uint8_t* we = g_W8 + (size_t)e * 1024;
    float acc = 0.f;
#pragma unroll
    for (int h = 0; h < 16; h++) {
        float2 vv;
        vv.x = __shfl_sync(0xffffffffu, v, 2 * h);
        vv.y = __shfl_sync(0xffffffffu, v, 2 * h + 1);
        uint16_t p0 = (uint16_t)we[(2 * h) * 32 + lane];
        uint16_t p1 = (uint16_t)we[(2 * h + 1) * 32 + lane];
        float2 w0 = e4m3x2_to_f2((uint16_t)(p0 | (p1 << 8)));
        acc += vv.x * w0.x + vv.y * w0.y;
    }
    atomicAdd(&g_neigh[dst[e] * 32 + lane], acc);
}

// ---------------- node update ----------------
__global__ void k_node(const float* __restrict__ mw, const float* __restrict__ mb,
                       const float* __restrict__ cb, const float* __restrict__ cur,
                       float* __restrict__ nxt) {
    __shared__ float s_w[2048];
    __shared__ float s_b[32], s_cb[32];
    for (int i = threadIdx.x; i < 2048; i += blockDim.x) s_w[i] = mw[i];
    if (threadIdx.x < 32) { s_b[threadIdx.x] = mb[threadIdx.x]; s_cb[threadIdx.x] = cb[threadIdx.x]; }
    __syncthreads();
    int i = blockIdx.x * blockDim.x + threadIdx.x;
    if (i >= NN) return;
    float dc = g_degc[i];
    float o[32], m[32];
#pragma unroll
    for (int h = 0; h < 32; h++) o[h] = cur[i * 32 + h];
#pragma unroll
    for (int h = 0; h < 32; h++)
        m[h] = fmaxf(g_neigh[i * 32 + h] / dc + o[h] + s_cb[h], 0.f);
#pragma unroll
    for (int j = 0; j < 32; j++) {
        float a = s_b[j];
#pragma unroll
        for (int h = 0; h < 32; h++) a += m[h] * s_w[h * 32 + j];
#pragma unroll
        for (int h = 0; h < 32; h++) a += o[h] * s_w[(32 + h) * 32 + j];
        nxt[i * 32 + j] = a;
    }
}

// ---------------- group pooling ----------------
__global__ void k_group(const int* __restrict__ src, const int* __restrict__ dst,
                        const float* __restrict__ cur) {
    int t = blockIdx.x * blockDim.x + threadIdx.x;
    int e = t >> 5;
    int lane = t & 31;
    if (e >= EE) return;
    atomicAdd(&g_neigh[dst[e] * 32 + lane], cur[src[e] * 32 + lane]);
}

// ---------------- final ----------------
__global__ void k_final(const float* __restrict__ sw, const float* __restrict__ sb,
                        const float* __restrict__ cur, float* __restrict__ outp) {
    __shared__ float s_w[2048];
    __shared__ float s_b[32];
    for (int i = threadIdx.x; i < 2048; i += blockDim.x) s_w[i] = sw[i];
    if (threadIdx.x < 32) s_b[threadIdx.x] = sb[threadIdx.x];
    __syncthreads();
    int i = blockIdx.x * blockDim.x + threadIdx.x;
    if (i >= NN) return;
    float dc = g_degc[i];
    float o[32], g[32];
#pragma unroll
    for (int h = 0; h < 32; h++) o[h] = cur[i * 32 + h];
#pragma unroll
    for (int h = 0; h < 32; h++) g[h] = g_neigh[i * 32 + h] / dc;
#pragma unroll
    for (int j = 0; j < 32; j++) {
        float a = s_b[j];
#pragma unroll
        for (int h = 0; h < 32; h++) a += o[h] * s_w[h * 32 + j];
#pragma unroll
        for (int h = 0; h < 32; h++) a += g[h] * s_w[(32 + h) * 32 + j];
        outp[i * 32 + j] = a + g_nf[i * 32 + j];
    }
}

// ---------------- side stream + events, created at program load ----------------
struct SideStream {
    cudaStream_t s2 = nullptr;
    cudaEvent_t fork = nullptr, join = nullptr;
    SideStream() {
        cudaStreamCreateWithFlags(&s2, cudaStreamNonBlocking);
        cudaEventCreateWithFlags(&fork, cudaEventDisableTiming);
        cudaEventCreateWithFlags(&join, cudaEventDisableTiming);
        float* p = nullptr;
        cudaGetSymbolAddress((void**)&p, g_deg);
        if (p) k_zero<<<1, 32, 0, s2>>>(p, 32);
        cudaEventRecord(fork, s2);
        cudaStreamSynchronize(s2);
    }
};
static SideStream g_ss;

// ---------------- launch ----------------
extern "C" void kernel_launch(void* const* d_in, const int* in_sizes, int n_in,
                              void* d_out, int out_size) {
    const float* n_feat = (const float*)d_in[0];
    const float* e_feat = (const float*)d_in[1];
    const int*   src    = (const int*)d_in[2];
    const int*   dst    = (const int*)d_in[3];
    const float* epw    = (const float*)d_in[4];
    const float* epb    = (const float*)d_in[5];
    const float* gw     = (const float*)d_in[6];
    const float* gb     = (const float*)d_in[7];
    const float* lw     = (const float*)d_in[8];
    const float* lb     = (const float*)d_in[9];
    const float* cb     = (const float*)d_in[10];
    const float* mw     = (const float*)d_in[11];
    const float* mb     = (const float*)d_in[12];
    const float* sw     = (const float*)d_in[13];
    const float* sb     = (const float*)d_in[14];
    float* outp = (float*)d_out;

    float *pA, *pB, *pDeg, *pNeigh, *pRwse;
    cudaGetSymbolAddress((void**)&pA, g_outA);
    cudaGetSymbolAddress((void**)&pB, g_outB);
    cudaGetSymbolAddress((void**)&pDeg, g_deg);
    cudaGetSymbolAddress((void**)&pNeigh, g_neigh);
    cudaGetSymbolAddress((void**)&pRwse, g_rwse);

    static int attr_set = 0;
    if (!attr_set) {
        cudaFuncSetAttribute(k_gemm_fp8, cudaFuncAttributeMaxDynamicSharedMemorySize, SMEM_DYN);
        attr_set = 1;
    }

    const int T = 256;
    const int gN  = (NN + T - 1) / T;
    const int gE  = (EE + T - 1) / T;
    const int gEW = (EE * 32 + T - 1) / T;
    cudaStream_t s2 = g_ss.s2;

    // ---- fork: side branch (degrees + RWSE + lin0 + neigh zero) alongside GEMM branch
    cudaEventRecord(g_ss.fork, 0);
    cudaStreamWaitEvent(s2, g_ss.fork, 0);

    // branch B (stream s2): everything independent of W
    k_zero<<<gN, T, 0, s2>>>(pDeg, NN);
    k_zero<<<(NN * 16 + T - 1) / T, T, 0, s2>>>(pRwse, NN * 16);
    k_zero<<<(NN * 32 + T - 1) / T, T, 0, s2>>>(pNeigh, NN * 32);
    k_deg<<<gE, T, 0, s2>>>(dst);
    k_degc<<<gN, T, 0, s2>>>();
    for (int k = 1; k < 16; k++)
        k_rwse_scatter<<<gE, T, 0, s2>>>(src, dst, k);
    k_lin0<<<gN, T, 0, s2>>>(n_feat, lw, lb);
    cudaEventRecord(g_ss.join, s2);

    // branch A (default stream): edge-conditioned weight pipeline (dominant)
    k_transB8<<<dim3(32, 32), dim3(32, 8)>>>(epw);
    k_convA8<<<(MPAD * 64 + T - 1) / T, T>>>(e_feat);
    k_gate8<<<gEW, T>>>(gw, gb);
    {
        dim3 grid(1024 / BN, MPAD / BM);
        k_gemm_fp8<<<grid, 256, SMEM_DYN>>>(epb);
    }

    // ---- join: msg needs both W (branch A) and outA/neigh (branch B)
    cudaStreamWaitEvent(0, g_ss.join, 0);

    // --- 3 NNConv steps (default stream) ---
    float* cur = pA;
    float* nxt = pB;
    for (int s = 0; s < 3; s++) {
        if (s > 0)
            k_zero<<<(NN * 32 + T - 1) / T, T>>>(pNeigh, NN * 32);
        k_msg<<<gEW, T>>>(src, dst, cur);
        k_node<<<gN, T>>>(mw, mb, cb, cur, nxt);
        float* t2 = cur; cur = nxt; nxt = t2;
    }

    // --- pooling + final ---
    k_zero<<<(NN * 32 + T - 1) / T, T>>>(pNeigh, NN * 32);
    k_group<<<gEW, T>>>(src, dst, cur);
    k_final<<<gN, T>>>(sw, sb, cur, outp);
}

// round 16
// speedup vs baseline: 1.0165x; 1.0165x over previous
#include <cuda_runtime.h>
#include <cuda_bf16.h>
#include <cuda_fp16.h>
#include <math.h>
#include <stdint.h>

#define NN 50000
#define EE 100000
#define MPAD 100096   // EE padded to multiple of 128
// H = 32, ED = 1024, K_RWSE = 16

typedef __nv_bfloat16 bf16;

#define BSCALE 16.0f            // pre-scale for edge_proj_w before e4m3 quantization
#define BSCALE_INV (1.0f / 16.0f)

// ---------------- scratch (device globals; no allocations allowed) ----------------
__device__ uint8_t  g_W8[(size_t)EE * 1024];    // edge-conditioned weights, e4m3 (~102MB)
__device__ uint8_t  g_A8[(size_t)MPAD * 1024];  // e_feat in e4m3, padded rows zero (~102MB)
__device__ uint8_t  g_Bt8[1024 * 1024];         // edge_proj_w^T * 16 in e4m3 (1MB)
__device__ float g_gate[EE];
__device__ float g_deg[NN];
__device__ float g_degc[NN];
__device__ float g_rwse[NN * 16];
__device__ float g_nf[NN * 32];
__device__ float g_outA[NN * 32];
__device__ float g_outB[NN * 32];
__device__ float g_neigh[NN * 32];

// ---------------- helpers ----------------
__device__ __forceinline__ void cp_async16(void* dst, const void* src) {
    uint32_t d = (uint32_t)__cvta_generic_to_shared(dst);
    asm volatile("cp.async.cg.shared.global [%0], [%1], 16;" :: "r"(d), "l"(src));
}

// pack 2 floats -> 2 e4m3 bytes (byte order a,b)
__device__ __forceinline__ uint16_t f2_to_e4m3(float a, float b) {
    uint16_t r;
    asm("cvt.rn.satfinite.e4m3x2.f32 %0, %1, %2;" : "=h"(r) : "f"(b), "f"(a));
    return r;
}

// pack 4 floats -> 4 e4m3 bytes, byte order a,b,c,d
__device__ __forceinline__ uint32_t f4_to_e4m3(float a, float b, float c, float d) {
    uint16_t lo = f2_to_e4m3(a, b);
    uint16_t hi = f2_to_e4m3(c, d);
    return (uint32_t)lo | ((uint32_t)hi << 16);
}

// unpack 2 e4m3 bytes -> float2
__device__ __forceinline__ float2 e4m3x2_to_f2(uint16_t v) {
    uint32_t h2;
    asm("cvt.rn.f16x2.e4m3x2 %0, %1;" : "=r"(h2) : "h"(v));
    __half2 hh = *reinterpret_cast<__half2*>(&h2);
    return __half22float2(hh);
}

__device__ __forceinline__ void mma_fp8(float* c, const uint32_t* a, const uint32_t* b) {
    asm volatile(
        "mma.sync.aligned.m16n8k32.row.col.f32.e4m3.e4m3.f32 "
        "{%0,%1,%2,%3}, {%4,%5,%6,%7}, {%8,%9}, {%0,%1,%2,%3};"
        : "+f"(c[0]), "+f"(c[1]), "+f"(c[2]), "+f"(c[3])
        : "r"(a[0]), "r"(a[1]), "r"(a[2]), "r"(a[3]), "r"(b[0]), "r"(b[1]));
}

// ---------------- small utility kernels ----------------
__global__ void k_zero(float* p, int n) {
    int i = blockIdx.x * blockDim.x + threadIdx.x;
    if (i < n) p[i] = 0.f;
}

__global__ void k_deg(const int* __restrict__ dst) {
    int e = blockIdx.x * blockDim.x + threadIdx.x;
    if (e < EE) atomicAdd(&g_deg[dst[e]], 1.0f);
}

__global__ void k_degc() {
    int i = blockIdx.x * blockDim.x + threadIdx.x;
    if (i < NN) {
        float d = g_deg[i];
        float dc = (d == 0.f) ? 1.f : d;
        g_degc[i] = dc;
        g_rwse[i * 16] = dc;   // col 0 of RWSE = degc
    }
}

// fused scatter: applies normalization of previous column on read
__global__ void k_rwse_scatter(const int* __restrict__ src, const int* __restrict__ dst, int k) {
    int e = blockIdx.x * blockDim.x + threadIdx.x;
    if (e >= EE) return;
    int s = src[e];
    float v = g_rwse[s * 16 + (k - 1)];
    if (k > 1) v /= g_degc[s];
    atomicAdd(&g_rwse[dst[e] * 16 + k], v);
}

// ---------------- convert e_feat -> e4m3 (padded rows zeroed) ----------------
__global__ void k_convA8(const float* __restrict__ A) {
    int i = blockIdx.x * blockDim.x + threadIdx.x;     // one 16B output per thread
    if (i >= MPAD * 64) return;
    int r = i >> 6;
    int c16 = (i & 63) << 4;
    uint32_t o[4];
    if (r < EE) {
        const float* p = A + (size_t)r * 1024 + c16;
#pragma unroll
        for (int j = 0; j < 4; j++) {
            float4 v = *(const float4*)(p + 4 * j);
            o[j] = f4_to_e4m3(v.x, v.y, v.z, v.w);
        }
    } else {
        o[0] = o[1] = o[2] = o[3] = 0u;
    }
    *(uint4*)(g_A8 + (size_t)r * 1024 + c16) = *(uint4*)o;
}

// ---------------- transpose + scale + convert edge_proj_w -> g_Bt8 [N][K] e4m3 ----------------
__global__ void k_transB8(const float* __restrict__ B) {
    __shared__ float t[32][33];
    int x0 = blockIdx.x * 32, y0 = blockIdx.y * 32;
    int tx = threadIdx.x, ty = threadIdx.y;  // 32 x 8
#pragma unroll
    for (int i = 0; i < 32; i += 8)
        t[ty + i][tx] = B[(size_t)(y0 + ty + i) * 1024 + x0 + tx];
    __syncthreads();
#pragma unroll
    for (int i = 0; i < 32; i += 8) {
        float v = t[tx][ty + i] * BSCALE;
        uint16_t pk = f2_to_e4m3(v, 0.f);
        g_Bt8[(size_t)(x0 + ty + i) * 1024 + y0 + tx] = (uint8_t)(pk & 0xFF);
    }
}

// ---------------- gate: sigmoid(A8 @ gate_w + gate_b), one warp per edge ----------------
__global__ void k_gate8(const float* __restrict__ gw, const float* __restrict__ gb) {
    int t = blockIdx.x * blockDim.x + threadIdx.x;
    int e = t >> 5;
    int lane = t & 31;
    if (e >= EE) return;
    const uint8_t* row = g_A8 + (size_t)e * 1024;
    float s = 0.f;
#pragma unroll
    for (int j = 0; j < 16; j++) {
        uint16_t pk = *(const uint16_t*)(row + j * 64 + 2 * lane);
        float2 v = e4m3x2_to_f2(pk);
        float2 g = *(const float2*)(gw + j * 64 + 2 * lane);
        s += v.x * g.x + v.y * g.y;
    }
#pragma unroll
    for (int off = 16; off > 0; off >>= 1)
        s += __shfl_down_sync(0xffffffffu, s, off);
    if (lane == 0) {
        float x = s + gb[0];
        g_gate[e] = 1.f / (1.f + expf(-x));
    }
}

// ---------------- fp8 GEMM, A-resident: one CTA per 128-row m-block, loops 4 n-blocks ----------------
// A (128 x 1024B) resident in smem; B streamed in 32 chunks (4 nb x 8 K-chunks), 2-buffer.
// A row stride 1040B (260 words, 260 mod 32 = 4 -> conflict-free frags).
// B chunk rows 144B (36 words) as before.
#define BM 128
#define BN 256
#define BKB 128
#define AROWB 1040
#define A_BYTES (BM * AROWB)              // 133120
#define BROWB 144
#define BSTAGE (BN * BROWB)               // 36864
#define SMEM_DYN (A_BYTES + 2 * BSTAGE)   // 206848

__global__ void __launch_bounds__(256, 1) k_gemm_fp8(const float* __restrict__ bias) {
    extern __shared__ uint8_t smem[];
    uint8_t* Asm = smem;
    uint8_t* Bsm = smem + A_BYTES;
    const int t = threadIdx.x;
    const int l = t & 31, w = t >> 5;
    const int wm = w & 1, wn = w >> 1;     // 2 warps M x 4 warps N
    const int g = l >> 2, t4 = l & 3;
    const int row0 = blockIdx.x * BM;

    auto load_B = [&](int q, int buf) {    // q = nb*8 + kc
        int nb = q >> 3, kc = q & 7;
        uint8_t* Bs = Bsm + buf * BSTAGE;
        const uint8_t* src = g_Bt8 + (size_t)(nb * BN) * 1024 + kc * BKB;
#pragma unroll
        for (int o = 0; o < 8; o++) {      // 2048 x 16B
            int lin = t + o * 256;
            int n = lin >> 3, c = lin & 7;
            cp_async16(Bs + n * BROWB + c * 16, src + (size_t)n * 1024 + c * 16);
        }
    };

    // prologue group 0: full A tile + B chunk 0
    {
#pragma unroll
        for (int o = 0; o < 32; o++) {     // A: 8192 x 16B
            int p = t + o * 256;
            int r = p >> 6, c16 = (p & 63) << 4;
            cp_async16(Asm + r * AROWB + c16, g_A8 + (size_t)(row0 + r) * 1024 + c16);
        }
        load_B(0, 0);
        asm volatile("cp.async.commit_group;");
    }

    float acc[4][8][4];
#pragma unroll
    for (int mt = 0; mt < 4; mt++)
#pragma unroll
        for (int nt = 0; nt < 8; nt++)
#pragma unroll
            for (int r = 0; r < 4; r++) acc[mt][nt][r] = 0.f;

    const uint32_t* As32 = (const uint32_t*)Asm;

    for (int q = 0; q < 32; q++) {
        int buf = q & 1;
        if (q + 1 < 32) {
            load_B(q + 1, buf ^ 1);
            asm volatile("cp.async.commit_group;");
            asm volatile("cp.async.wait_group 1;");
        } else {
            asm volatile("cp.async.wait_group 0;");
        }
        __syncthreads();

        const uint32_t* Bs32 = (const uint32_t*)(Bsm + buf * BSTAGE);
        const int kcw = (q & 7) * 32;      // A word-column base for this K-chunk
#pragma unroll
        for (int ks = 0; ks < 4; ks++) {
            const int kw = ks * 8 + t4;
            uint32_t a[4][4];
#pragma unroll
            for (int mt = 0; mt < 4; mt++) {
                int rw = wm * 64 + mt * 16 + g;
                a[mt][0] = As32[rw * 260 + kcw + kw];
                a[mt][1] = As32[(rw + 8) * 260 + kcw + kw];
                a[mt][2] = As32[rw * 260 + kcw + kw + 4];
                a[mt][3] = As32[(rw + 8) * 260 + kcw + kw + 4];
            }
            uint32_t b[8][2];
#pragma unroll
            for (int nt = 0; nt < 8; nt++) {
                int nr = wn * 64 + nt * 8 + g;
                b[nt][0] = Bs32[nr * 36 + kw];
                b[nt][1] = Bs32[nr * 36 + kw + 4];
            }
#pragma unroll
            for (int mt = 0; mt < 4; mt++)
#pragma unroll
                for (int nt = 0; nt < 8; nt++)
                    mma_fp8(acc[mt][nt], a[mt], b[nt]);
        }
        __syncthreads();

        if ((q & 7) == 7) {
            // epilogue for n-block nb = q>>3: e4m3(relu(acc/16 + bias) * gate) -> g_W8
            int col0 = (q >> 3) * BN;
#pragma unroll
            for (int mt = 0; mt < 4; mt++) {
                int r0 = row0 + wm * 64 + mt * 16 + g;
                int r1 = r0 + 8;
                float ga0 = (r0 < EE) ? g_gate[r0] : 0.f;
                float ga1 = (r1 < EE) ? g_gate[r1] : 0.f;
#pragma unroll
                for (int nt = 0; nt < 8; nt++) {
                    int cc = col0 + wn * 64 + nt * 8 + 2 * t4;
                    float2 bb = *(const float2*)&bias[cc];
                    if (r0 < EE) {
                        float x0 = fmaxf(acc[mt][nt][0] * BSCALE_INV + bb.x, 0.f) * ga0;
                        float x1 = fmaxf(acc[mt][nt][1] * BSCALE_INV + bb.y, 0.f) * ga0;
                        *(uint16_t*)(g_W8 + (size_t)r0 * 1024 + cc) = f2_to_e4m3(x0, x1);
                    }
                    if (r1 < EE) {
                        float x0 = fmaxf(acc[mt][nt][2] * BSCALE_INV + bb.x, 0.f) * ga1;
                        float x1 = fmaxf(acc[mt][nt][3] * BSCALE_INV + bb.y, 0.f) * ga1;
                        *(uint16_t*)(g_W8 + (size_t)r1 * 1024 + cc) = f2_to_e4m3(x0, x1);
                    }
                    // reset acc for next n-block
                    acc[mt][nt][0] = acc[mt][nt][1] = acc[mt][nt][2] = acc[mt][nt][3] = 0.f;
                }
            }
        }
    }
}

// ---------------- lin0 (applies RWSE normalization on read) ----------------
__global__ void k_lin0(const float* __restrict__ n_feat, const float* __restrict__ lw,
                       const float* __restrict__ lb) {
    __shared__ float s_w[1024];
    __shared__ float s_b[32];
    for (int i = threadIdx.x; i < 1024; i += blockDim.x) s_w[i] = lw[i];
    if (threadIdx.x < 32) s_b[threadIdx.x] = lb[threadIdx.x];
    __syncthreads();
    int i = blockIdx.x * blockDim.x + threadIdx.x;
    if (i >= NN) return;
    float dc = g_degc[i];
    float nf[32];
#pragma unroll
    for (int h = 0; h < 16; h++) nf[h] = n_feat[i * 16 + h];
    nf[16] = g_rwse[i * 16];
#pragma unroll
    for (int h = 1; h < 16; h++) nf[16 + h] = g_rwse[i * 16 + h] / dc;
#pragma unroll
    for (int h = 0; h < 32; h++) g_nf[i * 32 + h] = nf[h];
#pragma unroll
    for (int j = 0; j < 32; j++) {
        float a = s_b[j];
#pragma unroll
        for (int h = 0; h < 32; h++) a += nf[h] * s_w[h * 32 + j];
        g_outA[i * 32 + j] = fmaxf(a, 0.f);
    }
}

// ---------------- msg: warp per edge, W in e4m3 ----------------
__global__ void k_msg(const int* __restrict__ src, const int* __restrict__ dst,
                      const float* __restrict__ cur) {
    int t = blockIdx.x * blockDim.x + threadIdx.x;
    int e = t >> 5;
    int lane = t & 31;
    if (e >= EE) return;
    int s = src[e];
    float v = cur[s * 32 + lane];
    const uint8_t* we = g_W8 + (size_t)e * 1024;
    float acc = 0.f;
#pragma unroll
    for (int h = 0; h < 16; h++) {
        float2 vv;
        vv.x = __shfl_sync(0xffffffffu, v, 2 * h);
        vv.y = __shfl_sync(0xffffffffu, v, 2 * h + 1);
        uint16_t p0 = (uint16_t)we[(2 * h) * 32 + lane];
        uint16_t p1 = (uint16_t)we[(2 * h + 1) * 32 + lane];
        float2 w0 = e4m3x2_to_f2((uint16_t)(p0 | (p1 << 8)));
        acc += vv.x * w0.x + vv.y * w0.y;
    }
    atomicAdd(&g_neigh[dst[e] * 32 + lane], acc);
}

// ---------------- node update ----------------
__global__ void k_node(const float* __restrict__ mw, const float* __restrict__ mb,
                       const float* __restrict__ cb, const float* __restrict__ cur,
                       float* __restrict__ nxt) {
    __shared__ float s_w[2048];
    __shared__ float s_b[32], s_cb[32];
    for (int i = threadIdx.x; i < 2048; i += blockDim.x) s_w[i] = mw[i];
    if (threadIdx.x < 32) { s_b[threadIdx.x] = mb[threadIdx.x]; s_cb[threadIdx.x] = cb[threadIdx.x]; }
    __syncthreads();
    int i = blockIdx.x * blockDim.x + threadIdx.x;
    if (i >= NN) return;
    float dc = g_degc[i];
    float o[32], m[32];
#pragma unroll
    for (int h = 0; h < 32; h++) o[h] = cur[i * 32 + h];
#pragma unroll
    for (int h = 0; h < 32; h++)
        m[h] = fmaxf(g_neigh[i * 32 + h] / dc + o[h] + s_cb[h], 0.f);
#pragma unroll
    for (int j = 0; j < 32; j++) {
        float a = s_b[j];
#pragma unroll
        for (int h = 0; h < 32; h++) a += m[h] * s_w[h * 32 + j];
#pragma unroll
        for (int h = 0; h < 32; h++) a += o[h] * s_w[(32 + h) * 32 + j];
        nxt[i * 32 + j] = a;
    }
}

// ---------------- group pooling ----------------
__global__ void k_group(const int* __restrict__ src, const int* __restrict__ dst,
                        const float* __restrict__ cur) {
    int t = blockIdx.x * blockDim.x + threadIdx.x;
    int e = t >> 5;
    int lane = t & 31;
    if (e >= EE) return;
    atomicAdd(&g_neigh[dst[e] * 32 + lane], cur[src[e] * 32 + lane]);
}

// ---------------- final ----------------
__global__ void k_final(const float* __restrict__ sw, const float* __restrict__ sb,
                        const float* __restrict__ cur, float* __restrict__ outp) {
    __shared__ float s_w[2048];
    __shared__ float s_b[32];
    for (int i = threadIdx.x; i < 2048; i += blockDim.x) s_w[i] = sw[i];
    if (threadIdx.x < 32) s_b[threadIdx.x] = sb[threadIdx.x];
    __syncthreads();
    int i = blockIdx.x * blockDim.x + threadIdx.x;
    if (i >= NN) return;
    float dc = g_degc[i];
    float o[32], g[32];
#pragma unroll
    for (int h = 0; h < 32; h++) o[h] = cur[i * 32 + h];
#pragma unroll
    for (int h = 0; h < 32; h++) g[h] = g_neigh[i * 32 + h] / dc;
#pragma unroll
    for (int j = 0; j < 32; j++) {
        float a = s_b[j];
#pragma unroll
        for (int h = 0; h < 32; h++) a += o[h] * s_w[h * 32 + j];
#pragma unroll
        for (int h = 0; h < 32; h++) a += g[h] * s_w[(32 + h) * 32 + j];
        outp[i * 32 + j] = a + g_nf[i * 32 + j];
    }
}

// ---------------- side stream + events, created at program load ----------------
struct SideStream {
    cudaStream_t s2 = nullptr;
    cudaEvent_t fork = nullptr, join = nullptr;
    SideStream() {
        cudaStreamCreateWithFlags(&s2, cudaStreamNonBlocking);
        cudaEventCreateWithFlags(&fork, cudaEventDisableTiming);
        cudaEventCreateWithFlags(&join, cudaEventDisableTiming);
        float* p = nullptr;
        cudaGetSymbolAddress((void**)&p, g_deg);
        if (p) k_zero<<<1, 32, 0, s2>>>(p, 32);
        cudaEventRecord(fork, s2);
        cudaStreamSynchronize(s2);
    }
};
static SideStream g_ss;

// ---------------- launch ----------------
extern "C" void kernel_launch(void* const* d_in, const int* in_sizes, int n_in,
                              void* d_out, int out_size) {
    const float* n_feat = (const float*)d_in[0];
    const float* e_feat = (const float*)d_in[1];
    const int*   src    = (const int*)d_in[2];
    const int*   dst    = (const int*)d_in[3];
    const float* epw    = (const float*)d_in[4];
    const float* epb    = (const float*)d_in[5];
    const float* gw     = (const float*)d_in[6];
    const float* gb     = (const float*)d_in[7];
    const float* lw     = (const float*)d_in[8];
    const float* lb     = (const float*)d_in[9];
    const float* cb     = (const float*)d_in[10];
    const float* mw     = (const float*)d_in[11];
    const float* mb     = (const float*)d_in[12];
    const float* sw     = (const float*)d_in[13];
    const float* sb     = (const float*)d_in[14];
    float* outp = (float*)d_out;

    float *pA, *pB, *pDeg, *pNeigh, *pRwse;
    cudaGetSymbolAddress((void**)&pA, g_outA);
    cudaGetSymbolAddress((void**)&pB, g_outB);
    cudaGetSymbolAddress((void**)&pDeg, g_deg);
    cudaGetSymbolAddress((void**)&pNeigh, g_neigh);
    cudaGetSymbolAddress((void**)&pRwse, g_rwse);

    static int attr_set = 0;
    if (!attr_set) {
        cudaFuncSetAttribute(k_gemm_fp8, cudaFuncAttributeMaxDynamicSharedMemorySize, SMEM_DYN);
        attr_set = 1;
    }

    const int T = 256;
    const int gN  = (NN + T - 1) / T;
    const int gE  = (EE + T - 1) / T;
    const int gEW = (EE * 32 + T - 1) / T;
    cudaStream_t s2 = g_ss.s2;

    // ---- fork: side branch alongside GEMM branch
    cudaEventRecord(g_ss.fork, 0);
    cudaStreamWaitEvent(s2, g_ss.fork, 0);

    // branch B (stream s2): everything independent of W
    k_zero<<<gN, T, 0, s2>>>(pDeg, NN);
    k_zero<<<(NN * 16 + T - 1) / T, T, 0, s2>>>(pRwse, NN * 16);
    k_zero<<<(NN * 32 + T - 1) / T, T, 0, s2>>>(pNeigh, NN * 32);
    k_deg<<<gE, T, 0, s2>>>(dst);
    k_degc<<<gN, T, 0, s2>>>();
    for (int k = 1; k < 16; k++)
        k_rwse_scatter<<<gE, T, 0, s2>>>(src, dst, k);
    k_lin0<<<gN, T, 0, s2>>>(n_feat, lw, lb);
    cudaEventRecord(g_ss.join, s2);

    // branch A (default stream): edge-conditioned weight pipeline (dominant)
    k_transB8<<<dim3(32, 32), dim3(32, 8)>>>(epw);
    k_convA8<<<(MPAD * 64 + T - 1) / T, T>>>(e_feat);
    k_gate8<<<gEW, T>>>(gw, gb);
    k_gemm_fp8<<<MPAD / BM, 256, SMEM_DYN>>>(epb);

    // ---- join: msg needs both W (branch A) and outA/neigh (branch B)
    cudaStreamWaitEvent(0, g_ss.join, 0);

    // --- 3 NNConv steps (default stream) ---
    float* cur = pA;
    float* nxt = pB;
    for (int s = 0; s < 3; s++) {
        if (s > 0)
            k_zero<<<(NN * 32 + T - 1) / T, T>>>(pNeigh, NN * 32);
        k_msg<<<gEW, T>>>(src, dst, cur);
        k_node<<<gN, T>>>(mw, mb, cb, cur, nxt);
        float* t2 = cur; cur = nxt; nxt = t2;
    }

    // --- pooling + final ---
    k_zero<<<(NN * 32 + T - 1) / T, T>>>(pNeigh, NN * 32);
    k_group<<<gEW, T>>>(src, dst, cur);
    k_final<<<gN, T>>>(sw, sb, cur, outp);
}

// round 17
// speedup vs baseline: 1.1210x; 1.1028x over previous
#include <cuda_runtime.h>
#include <cuda_bf16.h>
#include <cuda_fp16.h>
#include <math.h>
#include <stdint.h>

#define NN 50000
#define EE 100000
#define MPAD 100096   // EE padded to multiple of 128
// H = 32, ED = 1024, K_RWSE = 16

typedef __nv_bfloat16 bf16;

#define BSCALE 16.0f            // pre-scale for edge_proj_w before e4m3 quantization
#define BSCALE_INV (1.0f / 16.0f)

// ---------------- scratch (device globals; no allocations allowed) ----------------
__device__ uint8_t  g_W8[(size_t)EE * 1024];    // edge-conditioned weights, e4m3 (~102MB)
__device__ uint8_t  g_A8[(size_t)MPAD * 1024];  // e_feat in e4m3, padded rows zero (~102MB)
__device__ uint8_t  g_Bt8[1024 * 1024];         // edge_proj_w^T * 16 in e4m3 (1MB)
__device__ float g_gate[EE];
__device__ float g_deg[NN];
__device__ float g_degc[NN];
__device__ float g_rwse[NN * 16];
__device__ float g_nf[NN * 32];
__device__ float g_outA[NN * 32];
__device__ float g_outB[NN * 32];
__device__ float g_neigh[NN * 32];

// ---------------- helpers ----------------
__device__ __forceinline__ void cp_async16(void* dst, const void* src) {
    uint32_t d = (uint32_t)__cvta_generic_to_shared(dst);
    asm volatile("cp.async.cg.shared.global [%0], [%1], 16;" :: "r"(d), "l"(src));
}

// pack 2 floats -> 2 e4m3 bytes (byte order a,b : a in low byte)
__device__ __forceinline__ uint16_t f2_to_e4m3(float a, float b) {
    uint16_t r;
    asm("cvt.rn.satfinite.e4m3x2.f32 %0, %1, %2;" : "=h"(r) : "f"(b), "f"(a));
    return r;
}

// pack 4 floats -> 4 e4m3 bytes, byte order a,b,c,d
__device__ __forceinline__ uint32_t f4_to_e4m3(float a, float b, float c, float d) {
    uint16_t lo = f2_to_e4m3(a, b);
    uint16_t hi = f2_to_e4m3(c, d);
    return (uint32_t)lo | ((uint32_t)hi << 16);
}

// unpack 2 e4m3 bytes -> float2 (.x = low byte)
__device__ __forceinline__ float2 e4m3x2_to_f2(uint16_t v) {
    uint32_t h2;
    asm("cvt.rn.f16x2.e4m3x2 %0, %1;" : "=r"(h2) : "h"(v));
    __half2 hh = *reinterpret_cast<__half2*>(&h2);
    return __half22float2(hh);
}

__device__ __forceinline__ void mma_fp8(float* c, const uint32_t* a, const uint32_t* b) {
    asm volatile(
        "mma.sync.aligned.m16n8k32.row.col.f32.e4m3.e4m3.f32 "
        "{%0,%1,%2,%3}, {%4,%5,%6,%7}, {%8,%9}, {%0,%1,%2,%3};"
        : "+f"(c[0]), "+f"(c[1]), "+f"(c[2]), "+f"(c[3])
        : "r"(a[0]), "r"(a[1]), "r"(a[2]), "r"(a[3]), "r"(b[0]), "r"(b[1]));
}

// ---------------- small utility kernels ----------------
__global__ void k_zero(float* p, int n) {
    int i = blockIdx.x * blockDim.x + threadIdx.x;
    if (i < n) p[i] = 0.f;
}

__global__ void k_deg(const int* __restrict__ dst) {
    int e = blockIdx.x * blockDim.x + threadIdx.x;
    if (e < EE) atomicAdd(&g_deg[dst[e]], 1.0f);
}

__global__ void k_degc() {
    int i = blockIdx.x * blockDim.x + threadIdx.x;
    if (i < NN) {
        float d = g_deg[i];
        float dc = (d == 0.f) ? 1.f : d;
        g_degc[i] = dc;
        g_rwse[i * 16] = dc;   // col 0 of RWSE = degc
    }
}

// fused scatter: applies normalization of previous column on read
__global__ void k_rwse_scatter(const int* __restrict__ src, const int* __restrict__ dst, int k) {
    int e = blockIdx.x * blockDim.x + threadIdx.x;
    if (e >= EE) return;
    int s = src[e];
    float v = g_rwse[s * 16 + (k - 1)];
    if (k > 1) v /= g_degc[s];
    atomicAdd(&g_rwse[dst[e] * 16 + k], v);
}

// ---------------- convert e_feat -> e4m3 (padded rows zeroed) ----------------
__global__ void k_convA8(const float* __restrict__ A) {
    int i = blockIdx.x * blockDim.x + threadIdx.x;     // one 16B output per thread
    if (i >= MPAD * 64) return;
    int r = i >> 6;
    int c16 = (i & 63) << 4;
    uint32_t o[4];
    if (r < EE) {
        const float* p = A + (size_t)r * 1024 + c16;
#pragma unroll
        for (int j = 0; j < 4; j++) {
            float4 v = *(const float4*)(p + 4 * j);
            o[j] = f4_to_e4m3(v.x, v.y, v.z, v.w);
        }
    } else {
        o[0] = o[1] = o[2] = o[3] = 0u;
    }
    *(uint4*)(g_A8 + (size_t)r * 1024 + c16) = *(uint4*)o;
}

// ---------------- transpose + scale + convert edge_proj_w -> g_Bt8 [N][K] e4m3 ----------------
__global__ void k_transB8(const float* __restrict__ B) {
    __shared__ float t[32][33];
    int x0 = blockIdx.x * 32, y0 = blockIdx.y * 32;
    int tx = threadIdx.x, ty = threadIdx.y;  // 32 x 8
#pragma unroll
    for (int i = 0; i < 32; i += 8)
        t[ty + i][tx] = B[(size_t)(y0 + ty + i) * 1024 + x0 + tx];
    __syncthreads();
#pragma unroll
    for (int i = 0; i < 32; i += 8) {
        float v = t[tx][ty + i] * BSCALE;
        uint16_t pk = f2_to_e4m3(v, 0.f);
        g_Bt8[(size_t)(x0 + ty + i) * 1024 + y0 + tx] = (uint8_t)(pk & 0xFF);
    }
}

// ---------------- gate: sigmoid(A8 @ gate_w + gate_b), one warp per edge ----------------
__global__ void k_gate8(const float* __restrict__ gw, const float* __restrict__ gb) {
    int t = blockIdx.x * blockDim.x + threadIdx.x;
    int e = t >> 5;
    int lane = t & 31;
    if (e >= EE) return;
    const uint8_t* row = g_A8 + (size_t)e * 1024;
    float s = 0.f;
#pragma unroll
    for (int j = 0; j < 16; j++) {
        uint16_t pk = *(const uint16_t*)(row + j * 64 + 2 * lane);
        float2 v = e4m3x2_to_f2(pk);
        float2 g = *(const float2*)(gw + j * 64 + 2 * lane);
        s += v.x * g.x + v.y * g.y;
    }
#pragma unroll
    for (int off = 16; off > 0; off >>= 1)
        s += __shfl_down_sync(0xffffffffu, s, off);
    if (lane == 0) {
        float x = s + gb[0];
        g_gate[e] = 1.f / (1.f + expf(-x));
    }
}

// ---------------- fp8 tensor-core GEMM (R14 exact: 128x256 tiles, 2-stage cp.async) ----------------
#define BM 128
#define BN 256
#define BKB 128                           // K per chunk, bytes (= elements)
#define SROWB 144                         // smem row stride, bytes
#define STAGE_BYTES ((BM + BN) * SROWB)   // 55296 B
#define SMEM_DYN (2 * STAGE_BYTES)        // 110592 B

__global__ void __launch_bounds__(256, 1) k_gemm_fp8(const float* __restrict__ bias) {
    extern __shared__ uint8_t smem[];
    const int t = threadIdx.x;
    const int l = t & 31, w = t >> 5;
    const int wm = w & 1, wn = w >> 1;     // 2 warps M x 4 warps N
    const int g = l >> 2, t4 = l & 3;
    const int row0 = blockIdx.y * BM;
    const int col0 = blockIdx.x * BN;

    float acc[4][8][4];
#pragma unroll
    for (int mt = 0; mt < 4; mt++)
#pragma unroll
        for (int nt = 0; nt < 8; nt++)
#pragma unroll
            for (int r = 0; r < 4; r++) acc[mt][nt][r] = 0.f;

    auto load_chunk = [&](int kb, int buf) {
        uint8_t* As = smem + buf * STAGE_BYTES;
        uint8_t* Bs = As + BM * SROWB;
#pragma unroll
        for (int o = 0; o < 4; o++) {              // A: 128 rows x 128B = 1024 x16B
            int lin = t + o * 256;
            int m = lin >> 3, c = lin & 7;
            cp_async16(As + m * SROWB + c * 16, g_A8 + (size_t)(row0 + m) * 1024 + kb + c * 16);
        }
#pragma unroll
        for (int o = 0; o < 8; o++) {              // B: 256 rows x 128B = 2048 x16B
            int lin = t + o * 256;
            int n = lin >> 3, c = lin & 7;
            cp_async16(Bs + n * SROWB + c * 16, g_Bt8 + (size_t)(col0 + n) * 1024 + kb + c * 16);
        }
    };

    load_chunk(0, 0);
    asm volatile("cp.async.commit_group;");

    const int NCH = 1024 / BKB;  // 8
    for (int c = 0; c < NCH; c++) {
        int buf = c & 1;
        if (c + 1 < NCH) {
            load_chunk((c + 1) * BKB, buf ^ 1);
            asm volatile("cp.async.commit_group;");
            asm volatile("cp.async.wait_group 1;");
        } else {
            asm volatile("cp.async.wait_group 0;");
        }
        __syncthreads();

        const uint32_t* As32 = (const uint32_t*)(smem + buf * STAGE_BYTES);
        const uint32_t* Bs32 = As32 + BM * (SROWB / 4);
#pragma unroll
        for (int ks = 0; ks < 4; ks++) {           // k32 per mma, 128B chunk -> 4 iters
            const int kw = ks * 8 + t4;            // word index in 32-word row
            uint32_t a[4][4];
#pragma unroll
            for (int mt = 0; mt < 4; mt++) {
                int rw = wm * 64 + mt * 16 + g;
                a[mt][0] = As32[rw * 36 + kw];
                a[mt][1] = As32[(rw + 8) * 36 + kw];
                a[mt][2] = As32[rw * 36 + kw + 4];
                a[mt][3] = As32[(rw + 8) * 36 + kw + 4];
            }
            uint32_t b[8][2];
#pragma unroll
            for (int nt = 0; nt < 8; nt++) {
                int nr = wn * 64 + nt * 8 + g;
                b[nt][0] = Bs32[nr * 36 + kw];
                b[nt][1] = Bs32[nr * 36 + kw + 4];
            }
#pragma unroll
            for (int mt = 0; mt < 4; mt++)
#pragma unroll
                for (int nt = 0; nt < 8; nt++)
                    mma_fp8(acc[mt][nt], a[mt], b[nt]);
        }
        __syncthreads();
    }

    // epilogue: e4m3(relu(acc/16 + bias) * gate) -> g_W8
#pragma unroll
    for (int mt = 0; mt < 4; mt++) {
        int r0 = row0 + wm * 64 + mt * 16 + g;
        int r1 = r0 + 8;
        float ga0 = (r0 < EE) ? g_gate[r0] : 0.f;
        float ga1 = (r1 < EE) ? g_gate[r1] : 0.f;
#pragma unroll
        for (int nt = 0; nt < 8; nt++) {
            int cc = col0 + wn * 64 + nt * 8 + 2 * t4;
            float2 bb = *(const float2*)&bias[cc];
            if (r0 < EE) {
                float x0 = fmaxf(acc[mt][nt][0] * BSCALE_INV + bb.x, 0.f) * ga0;
                float x1 = fmaxf(acc[mt][nt][1] * BSCALE_INV + bb.y, 0.f) * ga0;
                *(uint16_t*)(g_W8 + (size_t)r0 * 1024 + cc) = f2_to_e4m3(x0, x1);
            }
            if (r1 < EE) {
                float x0 = fmaxf(acc[mt][nt][2] * BSCALE_INV + bb.x, 0.f) * ga1;
                float x1 = fmaxf(acc[mt][nt][3] * BSCALE_INV + bb.y, 0.f) * ga1;
                *(uint16_t*)(g_W8 + (size_t)r1 * 1024 + cc) = f2_to_e4m3(x0, x1);
            }
        }
    }
}

// ---------------- lin0 (applies RWSE normalization on read) ----------------
__global__ void k_lin0(const float* __restrict__ n_feat, const float* __restrict__ lw,
                       const float* __restrict__ lb) {
    __shared__ float s_w[1024];
    __shared__ float s_b[32];
    for (int i = threadIdx.x; i < 1024; i += blockDim.x) s_w[i] = lw[i];
    if (threadIdx.x < 32) s_b[threadIdx.x] = lb[threadIdx.x];
    __syncthreads();
    int i = blockIdx.x * blockDim.x + threadIdx.x;
    if (i >= NN) return;
    float dc = g_degc[i];
    float nf[32];
#pragma unroll
    for (int h = 0; h < 16; h++) nf[h] = n_feat[i * 16 + h];
    nf[16] = g_rwse[i * 16];
#pragma unroll
    for (int h = 1; h < 16; h++) nf[16 + h] = g_rwse[i * 16 + h] / dc;
#pragma unroll
    for (int h = 0; h < 32; h++) g_nf[i * 32 + h] = nf[h];
#pragma unroll
    for (int j = 0; j < 32; j++) {
        float a = s_b[j];
#pragma unroll
        for (int h = 0; h < 32; h++) a += nf[h] * s_w[h * 32 + j];
        g_outA[i * 32 + j] = fmaxf(a, 0.f);
    }
}

// ---------------- msg: warp per edge, W in e4m3, u16 column-pair loads ----------------
// lane L owns columns (2*(L&15), 2*(L&15)+1); rows h = 2*hb + (L>>4).
// After the loop, lanes L and L^16 hold complementary h-parity partials -> shfl_xor(16).
// Each lane issues exactly ONE atomicAdd: lanes 0-15 even columns, 16-31 odd columns.
__global__ void k_msg(const int* __restrict__ src, const int* __restrict__ dst,
                      const float* __restrict__ cur) {
    int t = blockIdx.x * blockDim.x + threadIdx.x;
    int e = t >> 5;
    int lane = t & 31;
    if (e >= EE) return;
    int s = src[e];
    float v = cur[s * 32 + lane];          // v_lane = out[s][lane]
    const uint8_t* we = g_W8 + (size_t)e * 1024;
    const int c0 = 2 * (lane & 15);
    const int hp = lane >> 4;              // h parity for this lane
    float acc0 = 0.f, acc1 = 0.f;
#pragma unroll
    for (int hb = 0; hb < 16; hb++) {
        int h = 2 * hb + hp;
        float vh = __shfl_sync(0xffffffffu, v, h);
        uint16_t pk = *(const uint16_t*)(we + h * 32 + c0);
        float2 w2 = e4m3x2_to_f2(pk);      // .x = col c0, .y = col c0+1
        acc0 += vh * w2.x;
        acc1 += vh * w2.y;
    }
    acc0 += __shfl_xor_sync(0xffffffffu, acc0, 16);
    acc1 += __shfl_xor_sync(0xffffffffu, acc1, 16);
    float* nrow = &g_neigh[dst[e] * 32];
    if (lane < 16) atomicAdd(nrow + c0, acc0);
    else           atomicAdd(nrow + c0 + 1, acc1);
}

// ---------------- node update ----------------
__global__ void k_node(const float* __restrict__ mw, const float* __restrict__ mb,
                       const float* __restrict__ cb, const float* __restrict__ cur,
                       float* __restrict__ nxt) {
    __shared__ float s_w[2048];
    __shared__ float s_b[32], s_cb[32];
    for (int i = threadIdx.x; i < 2048; i += blockDim.x) s_w[i] = mw[i];
    if (threadIdx.x < 32) { s_b[threadIdx.x] = mb[threadIdx.x]; s_cb[threadIdx.x] = cb[threadIdx.x]; }
    __syncthreads();
    int i = blockIdx.x * blockDim.x + threadIdx.x;
    if (i >= NN) return;
    float dc = g_degc[i];
    float o[32], m[32];
#pragma unroll
    for (int h = 0; h < 32; h++) o[h] = cur[i * 32 + h];
#pragma unroll
    for (int h = 0; h < 32; h++)
        m[h] = fmaxf(g_neigh[i * 32 + h] / dc + o[h] + s_cb[h], 0.f);
#pragma unroll
    for (int j = 0; j < 32; j++) {
        float a = s_b[j];
#pragma unroll
        for (int h = 0; h < 32; h++) a += m[h] * s_w[h * 32 + j];
#pragma unroll
        for (int h = 0; h < 32; h++) a += o[h] * s_w[(32 + h) * 32 + j];
        nxt[i * 32 + j] = a;
    }
}

// ---------------- group pooling ----------------
__global__ void k_group(const int* __restrict__ src, const int* __restrict__ dst,
                        const float* __restrict__ cur) {
    int t = blockIdx.x * blockDim.x + threadIdx.x;
    int e = t >> 5;
    int lane = t & 31;
    if (e >= EE) return;
    atomicAdd(&g_neigh[dst[e] * 32 + lane], cur[src[e] * 32 + lane]);
}

// ---------------- final ----------------
__global__ void k_final(const float* __restrict__ sw, const float* __restrict__ sb,
                        const float* __restrict__ cur, float* __restrict__ outp) {
    __shared__ float s_w[2048];
    __shared__ float s_b[32];
    for (int i = threadIdx.x; i < 2048; i += blockDim.x) s_w[i] = sw[i];
    if (threadIdx.x < 32) s_b[threadIdx.x] = sb[threadIdx.x];
    __syncthreads();
    int i = blockIdx.x * blockDim.x + threadIdx.x;
    if (i >= NN) return;
    float dc = g_degc[i];
    float o[32], g[32];
#pragma unroll
    for (int h = 0; h < 32; h++) o[h] = cur[i * 32 + h];
#pragma unroll
    for (int h = 0; h < 32; h++) g[h] = g_neigh[i * 32 + h] / dc;
#pragma unroll
    for (int j = 0; j < 32; j++) {
        float a = s_b[j];
#pragma unroll
        for (int h = 0; h < 32; h++) a += o[h] * s_w[h * 32 + j];
#pragma unroll
        for (int h = 0; h < 32; h++) a += g[h] * s_w[(32 + h) * 32 + j];
        outp[i * 32 + j] = a + g_nf[i * 32 + j];
    }
}

// ---------------- side stream + events, created at program load ----------------
struct SideStream {
    cudaStream_t s2 = nullptr;
    cudaEvent_t fork = nullptr, join = nullptr;
    SideStream() {
        cudaStreamCreateWithFlags(&s2, cudaStreamNonBlocking);
        cudaEventCreateWithFlags(&fork, cudaEventDisableTiming);
        cudaEventCreateWithFlags(&join, cudaEventDisableTiming);
        float* p = nullptr;
        cudaGetSymbolAddress((void**)&p, g_deg);
        if (p) k_zero<<<1, 32, 0, s2>>>(p, 32);
        cudaEventRecord(fork, s2);
        cudaStreamSynchronize(s2);
    }
};
static SideStream g_ss;

// ---------------- launch ----------------
extern "C" void kernel_launch(void* const* d_in, const int* in_sizes, int n_in,
                              void* d_out, int out_size) {
    const float* n_feat = (const float*)d_in[0];
    const float* e_feat = (const float*)d_in[1];
    const int*   src    = (const int*)d_in[2];
    const int*   dst    = (const int*)d_in[3];
    const float* epw    = (const float*)d_in[4];
    const float* epb    = (const float*)d_in[5];
    const float* gw     = (const float*)d_in[6];
    const float* gb     = (const float*)d_in[7];
    const float* lw     = (const float*)d_in[8];
    const float* lb     = (const float*)d_in[9];
    const float* cb     = (const float*)d_in[10];
    const float* mw     = (const float*)d_in[11];
    const float* mb     = (const float*)d_in[12];
    const float* sw     = (const float*)d_in[13];
    const float* sb     = (const float*)d_in[14];
    float* outp = (float*)d_out;

    float *pA, *pB, *pDeg, *pNeigh, *pRwse;
    cudaGetSymbolAddress((void**)&pA, g_outA);
    cudaGetSymbolAddress((void**)&pB, g_outB);
    cudaGetSymbolAddress((void**)&pDeg, g_deg);
    cudaGetSymbolAddress((void**)&pNeigh, g_neigh);
    cudaGetSymbolAddress((void**)&pRwse, g_rwse);

    static int attr_set = 0;
    if (!attr_set) {
        cudaFuncSetAttribute(k_gemm_fp8, cudaFuncAttributeMaxDynamicSharedMemorySize, SMEM_DYN);
        attr_set = 1;
    }

    const int T = 256;
    const int gN  = (NN + T - 1) / T;
    const int gE  = (EE + T - 1) / T;
    const int gEW = (EE * 32 + T - 1) / T;
    cudaStream_t s2 = g_ss.s2;

    // ---- fork: side branch alongside GEMM branch
    cudaEventRecord(g_ss.fork, 0);
    cudaStreamWaitEvent(s2, g_ss.fork, 0);

    // branch B (stream s2): everything independent of W
    k_zero<<<gN, T, 0, s2>>>(pDeg, NN);
    k_zero<<<(NN * 16 + T - 1) / T, T, 0, s2>>>(pRwse, NN * 16);
    k_zero<<<(NN * 32 + T - 1) / T, T, 0, s2>>>(pNeigh, NN * 32);
    k_deg<<<gE, T, 0, s2>>>(dst);
    k_degc<<<gN, T, 0, s2>>>();
    for (int k = 1; k < 16; k++)
        k_rwse_scatter<<<gE, T, 0, s2>>>(src, dst, k);
    k_lin0<<<gN, T, 0, s2>>>(n_feat, lw, lb);
    cudaEventRecord(g_ss.join, s2);

    // branch A (default stream): edge-conditioned weight pipeline (dominant)
    k_transB8<<<dim3(32, 32), dim3(32, 8)>>>(epw);
    k_convA8<<<(MPAD * 64 + T - 1) / T, T>>>(e_feat);
    k_gate8<<<gEW, T>>>(gw, gb);
    {
        dim3 grid(1024 / BN, MPAD / BM);
        k_gemm_fp8<<<grid, 256, SMEM_DYN>>>(epb);
    }

    // ---- join: msg needs both W (branch A) and outA/neigh (branch B)
    cudaStreamWaitEvent(0, g_ss.join, 0);

    // --- 3 NNConv steps (default stream) ---
    float* cur = pA;
    float* nxt = pB;
    for (int s = 0; s < 3; s++) {
        if (s > 0)
            k_zero<<<(NN * 32 + T - 1) / T, T>>>(pNeigh, NN * 32);
        k_msg<<<gEW, T>>>(src, dst, cur);
        k_node<<<gN, T>>>(mw, mb, cb, cur, nxt);
        float* t2 = cur; cur = nxt; nxt = t2;
    }

    // --- pooling + final ---
    k_zero<<<(NN * 32 + T - 1) / T, T>>>(pNeigh, NN * 32);
    k_group<<<gEW, T>>>(src, dst, cur);
    k_final<<<gN, T>>>(sw, sb, cur, outp);
}